// round 7
// baseline (speedup 1.0000x reference)
#include <cuda_runtime.h>
#include <cstdint>

#define BATCH 8
#define SEQ   1024
#define DMODEL 512
#define NHEAD 8
#define HDIM  64

// tf32 tensor-core tile config (non-pipelined kernels)
#define TCPAD 68
#define TC_SMEM_BYTES (2 * 128 * TCPAD * 4)
#define AV_SMEM_BYTES ((128 * TCPAD + 64 * TCPAD) * 4)

// pipelined projection kernel
#define PSTR 36                              // smem row stride (floats), 36 mod 32 == 4
#define P4_STAGE_WORDS (2 * 128 * PSTR)      // A + B per stage
#define P4_SMEM_BYTES  (2 * P4_STAGE_WORDS * 4)   // 2 stages = 73728 B

static __device__ float g_qu [(size_t)BATCH*NHEAD*SEQ*HDIM];
static __device__ float g_qvb[(size_t)BATCH*NHEAD*SEQ*HDIM];
static __device__ float g_kh [(size_t)BATCH*NHEAD*SEQ*HDIM];
static __device__ float g_vh [(size_t)BATCH*NHEAD*SEQ*HDIM];
static __device__ float g_ph [(size_t)BATCH*NHEAD*SEQ*HDIM];
static __device__ float g_ctx[(size_t)BATCH*SEQ*DMODEL];
static __device__ float g_pos[(size_t)BATCH*NHEAD*SEQ*SEQ];

__device__ __forceinline__ uint32_t f2tf32(float x) {
    uint32_t t;
    asm("cvt.rna.tf32.f32 %0, %1;" : "=r"(t) : "f"(x));
    return t;
}

__device__ __forceinline__ void mma_tf32(float c[4], const uint32_t a[4], const uint32_t b[2]) {
    asm volatile(
        "mma.sync.aligned.m16n8k8.row.col.f32.tf32.tf32.f32 "
        "{%0,%1,%2,%3}, {%4,%5,%6,%7}, {%8,%9}, {%0,%1,%2,%3};"
        : "+f"(c[0]), "+f"(c[1]), "+f"(c[2]), "+f"(c[3])
        : "r"(a[0]), "r"(a[1]), "r"(a[2]), "r"(a[3]), "r"(b[0]), "r"(b[1]));
}

__device__ __forceinline__ void cp_async16(uint32_t saddr, const void* gptr) {
    asm volatile("cp.async.cg.shared.global [%0], [%1], 16;" :: "r"(saddr), "l"(gptr));
}
__device__ __forceinline__ void cp_commit() { asm volatile("cp.async.commit_group;"); }
template <int N>
__device__ __forceinline__ void cp_wait() { asm volatile("cp.async.wait_group %0;" :: "n"(N)); }

// ---------------------------------------------------------------------------
// Merged + pipelined TF32 projection: one launch for q/k/pos/v projections.
// blockIdx.z: 0=q (dual out +u/+v_bias), 1=k, 2=pos (no bias), 3=v.
// 128x128 block tile, K streamed in 32-chunks via 2-stage cp.async pipeline.
// Output scattered head-major [b][n][s][hd].
// ---------------------------------------------------------------------------
__global__ __launch_bounds__(256, 2)
void k_proj4_tc(const float* __restrict__ qin, const float* __restrict__ kin,
                const float* __restrict__ pin, const float* __restrict__ vin,
                const float* __restrict__ Wq, const float* __restrict__ bq,
                const float* __restrict__ Wk, const float* __restrict__ bk,
                const float* __restrict__ Wpos,
                const float* __restrict__ Wv, const float* __restrict__ bv,
                const float* __restrict__ u, const float* __restrict__ v_bias,
                float* __restrict__ O_qu, float* __restrict__ O_qvb,
                float* __restrict__ O_kh, float* __restrict__ O_ph,
                float* __restrict__ O_vh)
{
    extern __shared__ float smf[];

    const float *X, *W, *bias = nullptr, *add1 = nullptr, *add2 = nullptr;
    float *O1, *O2 = nullptr;
    switch (blockIdx.z) {
        case 0:  X = qin; W = Wq;   bias = bq; O1 = O_qu; add1 = u; O2 = O_qvb; add2 = v_bias; break;
        case 1:  X = kin; W = Wk;   bias = bk; O1 = O_kh; break;
        case 2:  X = pin; W = Wpos;            O1 = O_ph; break;
        default: X = vin; W = Wv;   bias = bv; O1 = O_vh; break;
    }

    const int tid = threadIdx.x;
    const int m0 = blockIdx.y * 128;
    const int n0 = blockIdx.x * 128;
    const int lane = tid & 31, warp = tid >> 5;
    const int wm = (warp & 1) * 64, wn = (warp >> 1) * 32;
    const int grp = lane >> 2, tig = lane & 3;

    // loader mapping: 2 threads per row, 16 floats (4x float4) each
    const int lrow = tid >> 1;
    const int lc   = (tid & 1) * 16;

    const float* Ag = X + (size_t)(m0 + lrow) * DMODEL + lc;
    const float* Bg = W + (size_t)(n0 + lrow) * DMODEL + lc;
    const uint32_t s0 = (uint32_t)__cvta_generic_to_shared(smf);
    const uint32_t sArow = s0 + (lrow * PSTR + lc) * 4;
    const uint32_t sBrow = sArow + 128 * PSTR * 4;

    float acc[4][4][4] = {};

    const int NK = DMODEL / 32;   // 16 chunks

    // prologue: load chunk 0 into stage 0
    {
#pragma unroll
        for (int j = 0; j < 4; j++) {
            cp_async16(sArow + j * 16, Ag + j * 4);
            cp_async16(sBrow + j * 16, Bg + j * 4);
        }
        cp_commit();
    }

    for (int t = 0; t < NK; t++) {
        const int cur = t & 1;
        if (t + 1 < NK) {
            const int nxt = cur ^ 1;
            const uint32_t off = (uint32_t)(nxt * P4_STAGE_WORDS * 4);
            const int k0 = (t + 1) * 32;
#pragma unroll
            for (int j = 0; j < 4; j++) {
                cp_async16(sArow + off + j * 16, Ag + k0 + j * 4);
                cp_async16(sBrow + off + j * 16, Bg + k0 + j * 4);
            }
            cp_commit();
            cp_wait<1>();
        } else {
            cp_wait<0>();
        }
        __syncthreads();

        const float* As = smf + cur * P4_STAGE_WORDS;
        const float* Bs = As + 128 * PSTR;

#pragma unroll
        for (int ks = 0; ks < 4; ks++) {
            const int kk = ks * 8;
            uint32_t a[4][4], b[4][2];
#pragma unroll
            for (int tm = 0; tm < 4; tm++) {
                int r = wm + tm * 16 + grp;
                a[tm][0] = f2tf32(As[r * PSTR + kk + tig]);
                a[tm][1] = f2tf32(As[(r + 8) * PSTR + kk + tig]);
                a[tm][2] = f2tf32(As[r * PSTR + kk + tig + 4]);
                a[tm][3] = f2tf32(As[(r + 8) * PSTR + kk + tig + 4]);
            }
#pragma unroll
            for (int tn = 0; tn < 4; tn++) {
                int c = wn + tn * 8 + grp;
                b[tn][0] = f2tf32(Bs[c * PSTR + kk + tig]);
                b[tn][1] = f2tf32(Bs[c * PSTR + kk + tig + 4]);
            }
#pragma unroll
            for (int tm = 0; tm < 4; tm++)
#pragma unroll
                for (int tn = 0; tn < 4; tn++)
                    mma_tf32(acc[tm][tn], a[tm], b[tn]);
        }
        __syncthreads();
    }

    // Epilogue: scatter to head-major [b][n][s][hd]
#pragma unroll
    for (int tm = 0; tm < 4; tm++) {
#pragma unroll
        for (int tn = 0; tn < 4; tn++) {
            int j = n0 + wn + tn * 8 + tig * 2;
            int hn = j >> 6, hd = j & (HDIM - 1);
            float bj0 = bias ? bias[j] : 0.0f;
            float bj1 = bias ? bias[j + 1] : 0.0f;
#pragma unroll
            for (int half = 0; half < 2; half++) {
                int m = m0 + wm + tm * 16 + grp + half * 8;
                int bb = m >> 10, s = m & (SEQ - 1);
                float v0 = acc[tm][tn][half * 2 + 0] + bj0;
                float v1 = acc[tm][tn][half * 2 + 1] + bj1;
                size_t off = (((size_t)bb * NHEAD + hn) * SEQ + s) * HDIM + hd;
                if (add1) {
                    *(float2*)&O1[off] = make_float2(v0 + add1[j], v1 + add1[j + 1]);
                } else {
                    *(float2*)&O1[off] = make_float2(v0, v1);
                }
                if (O2) {
                    *(float2*)&O2[off] = make_float2(v0 + add2[j], v1 + add2[j + 1]);
                }
            }
        }
    }
}

// ---------------------------------------------------------------------------
// TF32 batched score GEMM (NT, K=64): C[q,k] = sum_d A[q,d]*B[k,d]
// z in [0,64): content (qu x kh) -> C0 ; z in [64,128): pos (qvb x ph) -> C1
// ---------------------------------------------------------------------------
__global__ __launch_bounds__(256)
void k_scores_tc(const float* __restrict__ A0, const float* __restrict__ B0,
                 float* __restrict__ C0,
                 const float* __restrict__ A1, const float* __restrict__ B1,
                 float* __restrict__ C1)
{
    extern __shared__ uint32_t sm[];
    uint32_t* As = sm;
    uint32_t* Bs = sm + 128 * TCPAD;

    int z = blockIdx.z;
    const float *Aall, *Ball; float* Call;
    if (z < BATCH * NHEAD) { Aall = A0; Ball = B0; Call = C0; }
    else { z -= BATCH * NHEAD; Aall = A1; Ball = B1; Call = C1; }
    const float* X = Aall + (size_t)z * SEQ * HDIM;
    const float* W = Ball + (size_t)z * SEQ * HDIM;
    float* C = Call + (size_t)z * SEQ * SEQ;

    const int tid = threadIdx.x;
    const int m0 = blockIdx.y * 128;
    const int n0 = blockIdx.x * 128;
    const int lane = tid & 31, warp = tid >> 5;
    const int wm = (warp & 1) * 64, wn = (warp >> 1) * 32;
    const int grp = lane >> 2, tig = lane & 3;

    const int lrow  = tid >> 4;
    const int lcol4 = (tid & 15) * 4;

#pragma unroll
    for (int i = 0; i < 8; i++) {
        int r = lrow + i * 16;
        float4 a4 = *(const float4*)(X + (size_t)(m0 + r) * HDIM + lcol4);
        float4 b4 = *(const float4*)(W + (size_t)(n0 + r) * HDIM + lcol4);
        *(uint4*)&As[r * TCPAD + lcol4] =
            make_uint4(f2tf32(a4.x), f2tf32(a4.y), f2tf32(a4.z), f2tf32(a4.w));
        *(uint4*)&Bs[r * TCPAD + lcol4] =
            make_uint4(f2tf32(b4.x), f2tf32(b4.y), f2tf32(b4.z), f2tf32(b4.w));
    }
    __syncthreads();

    float acc[4][4][4] = {};
#pragma unroll
    for (int ks = 0; ks < 8; ks++) {
        const int kk = ks * 8;
        uint32_t a[4][4], b[4][2];
#pragma unroll
        for (int tm = 0; tm < 4; tm++) {
            int r = wm + tm * 16 + grp;
            a[tm][0] = As[r * TCPAD + kk + tig];
            a[tm][1] = As[(r + 8) * TCPAD + kk + tig];
            a[tm][2] = As[r * TCPAD + kk + tig + 4];
            a[tm][3] = As[(r + 8) * TCPAD + kk + tig + 4];
        }
#pragma unroll
        for (int tn = 0; tn < 4; tn++) {
            int c = wn + tn * 8 + grp;
            b[tn][0] = Bs[c * TCPAD + kk + tig];
            b[tn][1] = Bs[c * TCPAD + kk + tig + 4];
        }
#pragma unroll
        for (int tm = 0; tm < 4; tm++)
#pragma unroll
            for (int tn = 0; tn < 4; tn++)
                mma_tf32(acc[tm][tn], a[tm], b[tn]);
    }

#pragma unroll
    for (int tm = 0; tm < 4; tm++) {
#pragma unroll
        for (int tn = 0; tn < 4; tn++) {
            int col = n0 + wn + tn * 8 + tig * 2;
#pragma unroll
            for (int half = 0; half < 2; half++) {
                int row = m0 + wm + tm * 16 + grp + half * 8;
                *(float2*)&C[(size_t)row * SEQ + col] =
                    make_float2(acc[tm][tn][half * 2 + 0], acc[tm][tn][half * 2 + 1]);
            }
        }
    }
}

// ---------------------------------------------------------------------------
// TF32 batched AV GEMM (NN): Ctx[b][q][n*HDIM+d] = sum_k attn[z][q][k]*vh[z][k][d]
// ---------------------------------------------------------------------------
__global__ __launch_bounds__(256)
void k_av_tc(const float* __restrict__ Attn, const float* __restrict__ Vall,
             float* __restrict__ Ctx)
{
    extern __shared__ uint32_t sm[];
    uint32_t* As = sm;               // [128][TCPAD]
    uint32_t* Bs = sm + 128 * TCPAD; // [64][TCPAD]

    const int z = blockIdx.z;
    const int b = z >> 3, n = z & 7;
    const float* Ab = Attn + (size_t)z * SEQ * SEQ;
    const float* Bb = Vall + (size_t)z * SEQ * HDIM;

    const int tid = threadIdx.x;
    const int m0 = blockIdx.y * 128;
    const int lane = tid & 31, warp = tid >> 5;
    const int wm = (warp & 3) * 32, wn = (warp >> 2) * 32;
    const int grp = lane >> 2, tig = lane & 3;

    const int lrow  = tid >> 4;
    const int lcol4 = (tid & 15) * 4;

    float acc[2][4][4] = {};

    for (int k0 = 0; k0 < SEQ; k0 += 64) {
#pragma unroll
        for (int i = 0; i < 8; i++) {
            int r = lrow + i * 16;
            float4 a4 = *(const float4*)(Ab + (size_t)(m0 + r) * SEQ + k0 + lcol4);
            *(uint4*)&As[r * TCPAD + lcol4] =
                make_uint4(f2tf32(a4.x), f2tf32(a4.y), f2tf32(a4.z), f2tf32(a4.w));
        }
#pragma unroll
        for (int i = 0; i < 4; i++) {
            int r = lrow + i * 16;
            float4 b4 = *(const float4*)(Bb + (size_t)(k0 + r) * HDIM + lcol4);
            *(uint4*)&Bs[r * TCPAD + lcol4] =
                make_uint4(f2tf32(b4.x), f2tf32(b4.y), f2tf32(b4.z), f2tf32(b4.w));
        }
        __syncthreads();

#pragma unroll
        for (int ks = 0; ks < 8; ks++) {
            const int kk = ks * 8;
            uint32_t a[2][4], bfr[4][2];
#pragma unroll
            for (int tm = 0; tm < 2; tm++) {
                int r = wm + tm * 16 + grp;
                a[tm][0] = As[r * TCPAD + kk + tig];
                a[tm][1] = As[(r + 8) * TCPAD + kk + tig];
                a[tm][2] = As[r * TCPAD + kk + tig + 4];
                a[tm][3] = As[(r + 8) * TCPAD + kk + tig + 4];
            }
#pragma unroll
            for (int tn = 0; tn < 4; tn++) {
                int c = wn + tn * 8 + grp;
                bfr[tn][0] = Bs[(kk + tig) * TCPAD + c];
                bfr[tn][1] = Bs[(kk + tig + 4) * TCPAD + c];
            }
#pragma unroll
            for (int tm = 0; tm < 2; tm++)
#pragma unroll
                for (int tn = 0; tn < 4; tn++)
                    mma_tf32(acc[tm][tn], a[tm], bfr[tn]);
        }
        __syncthreads();
    }

#pragma unroll
    for (int tm = 0; tm < 2; tm++) {
#pragma unroll
        for (int tn = 0; tn < 4; tn++) {
            int d = wn + tn * 8 + tig * 2;
#pragma unroll
            for (int half = 0; half < 2; half++) {
                int qrow = m0 + wm + tm * 16 + grp + half * 8;
                *(float2*)&Ctx[((size_t)b * SEQ + qrow) * DMODEL + n * HDIM + d] =
                    make_float2(acc[tm][tn][half * 2 + 0], acc[tm][tn][half * 2 + 1]);
            }
        }
    }
}

// ---------------------------------------------------------------------------
// TF32 output NT GEMM: Out[m,j] = sum_d Ctx[m,d]*Wout[j,d] + bout[j] (row-major)
// ---------------------------------------------------------------------------
__global__ __launch_bounds__(256)
void k_out_tc(const float* __restrict__ X, const float* __restrict__ W,
              const float* __restrict__ bias, float* __restrict__ Out)
{
    extern __shared__ uint32_t sm[];
    uint32_t* As = sm;
    uint32_t* Bs = sm + 128 * TCPAD;

    const int tid = threadIdx.x;
    const int m0 = blockIdx.y * 128;
    const int n0 = blockIdx.x * 128;
    const int lane = tid & 31, warp = tid >> 5;
    const int wm = (warp & 1) * 64, wn = (warp >> 1) * 32;
    const int grp = lane >> 2, tig = lane & 3;

    const int lrow  = tid >> 4;
    const int lcol4 = (tid & 15) * 4;

    float acc[4][4][4] = {};

    for (int k0 = 0; k0 < DMODEL; k0 += 64) {
#pragma unroll
        for (int i = 0; i < 8; i++) {
            int r = lrow + i * 16;
            float4 a4 = *(const float4*)(X + (size_t)(m0 + r) * DMODEL + k0 + lcol4);
            float4 b4 = *(const float4*)(W + (size_t)(n0 + r) * DMODEL + k0 + lcol4);
            *(uint4*)&As[r * TCPAD + lcol4] =
                make_uint4(f2tf32(a4.x), f2tf32(a4.y), f2tf32(a4.z), f2tf32(a4.w));
            *(uint4*)&Bs[r * TCPAD + lcol4] =
                make_uint4(f2tf32(b4.x), f2tf32(b4.y), f2tf32(b4.z), f2tf32(b4.w));
        }
        __syncthreads();

#pragma unroll
        for (int ks = 0; ks < 8; ks++) {
            const int kk = ks * 8;
            uint32_t a[4][4], b[4][2];
#pragma unroll
            for (int tm = 0; tm < 4; tm++) {
                int r = wm + tm * 16 + grp;
                a[tm][0] = As[r * TCPAD + kk + tig];
                a[tm][1] = As[(r + 8) * TCPAD + kk + tig];
                a[tm][2] = As[r * TCPAD + kk + tig + 4];
                a[tm][3] = As[(r + 8) * TCPAD + kk + tig + 4];
            }
#pragma unroll
            for (int tn = 0; tn < 4; tn++) {
                int c = wn + tn * 8 + grp;
                b[tn][0] = Bs[c * TCPAD + kk + tig];
                b[tn][1] = Bs[c * TCPAD + kk + tig + 4];
            }
#pragma unroll
            for (int tm = 0; tm < 4; tm++)
#pragma unroll
                for (int tn = 0; tn < 4; tn++)
                    mma_tf32(acc[tm][tn], a[tm], b[tn]);
        }
        __syncthreads();
    }

#pragma unroll
    for (int tm = 0; tm < 4; tm++) {
#pragma unroll
        for (int tn = 0; tn < 4; tn++) {
            int j = n0 + wn + tn * 8 + tig * 2;
            float bj0 = bias[j], bj1 = bias[j + 1];
#pragma unroll
            for (int half = 0; half < 2; half++) {
                int m = m0 + wm + tm * 16 + grp + half * 8;
                *(float2*)&Out[(size_t)m * DMODEL + j] =
                    make_float2(acc[tm][tn][half * 2 + 0] + bj0,
                                acc[tm][tn][half * 2 + 1] + bj1);
            }
        }
    }
}

// ---------------------------------------------------------------------------
// Fused relative shift + scale + mask + softmax. One block per (b,n,q) row.
// shift[q,k] = pos[q, S-1-q+k] (k<=q); 0 (k==q+1); pos[q+1, k-q-2] (k>q+1)
// ---------------------------------------------------------------------------
__global__ __launch_bounds__(256)
void k_softmax(float* __restrict__ AttnOut, const float* __restrict__ Pos,
               const int* __restrict__ Mask)
{
    const int row = blockIdx.x;
    const int q = row & (SEQ - 1);
    const int z = row >> 10;
    const int b = z >> 3;

    float* Crow = AttnOut + (size_t)row * SEQ;
    const float* P0 = Pos + ((size_t)z * SEQ + q) * SEQ;
    const float* P1 = Pos + ((size_t)z * SEQ + q + 1) * SEQ;
    const int* Mrow = Mask + ((size_t)b * SEQ + q) * SEQ;

    const float scale = 0.04419417382415922f;  // 1/sqrt(512)
    const int tid = threadIdx.x;

    float vals[4];
    float lmax = -3.0e38f;
#pragma unroll
    for (int i = 0; i < 4; i++) {
        int k = tid + i * 256;
        float c = Crow[k];
        float p;
        if (k <= q)           p = P0[SEQ - 1 - q + k];
        else if (k == q + 1)  p = 0.0f;
        else                  p = P1[k - q - 2];
        float sc = (c + p) * scale;
        if (Mrow[k] != 0) sc = -10000.0f;
        vals[i] = sc;
        lmax = fmaxf(lmax, sc);
    }

    __shared__ float red[8];
#pragma unroll
    for (int o = 16; o; o >>= 1) lmax = fmaxf(lmax, __shfl_xor_sync(0xffffffffu, lmax, o));
    if ((tid & 31) == 0) red[tid >> 5] = lmax;
    __syncthreads();
    float bmax = red[0];
#pragma unroll
    for (int w = 1; w < 8; w++) bmax = fmaxf(bmax, red[w]);

    float lsum = 0.0f;
#pragma unroll
    for (int i = 0; i < 4; i++) {
        vals[i] = __expf(vals[i] - bmax);
        lsum += vals[i];
    }
#pragma unroll
    for (int o = 16; o; o >>= 1) lsum += __shfl_xor_sync(0xffffffffu, lsum, o);
    __syncthreads();
    if ((tid & 31) == 0) red[tid >> 5] = lsum;
    __syncthreads();
    float tot = 0.0f;
#pragma unroll
    for (int w = 0; w < 8; w++) tot += red[w];
    float inv = 1.0f / tot;

#pragma unroll
    for (int i = 0; i < 4; i++) {
        int k = tid + i * 256;
        Crow[k] = vals[i] * inv;
    }
}

extern "C" void kernel_launch(void* const* d_in, const int* in_sizes, int n_in,
                              void* d_out, int out_size)
{
    const float* q       = (const float*)d_in[0];
    const float* k       = (const float*)d_in[1];
    const float* v       = (const float*)d_in[2];
    const float* pos_emb = (const float*)d_in[3];
    const int*   mask    = (const int*)d_in[4];   // bool -> int32 in harness
    const float* Wq   = (const float*)d_in[5];
    const float* bq   = (const float*)d_in[6];
    const float* Wk   = (const float*)d_in[7];
    const float* bk   = (const float*)d_in[8];
    const float* Wv   = (const float*)d_in[9];
    const float* bv   = (const float*)d_in[10];
    const float* Wpos = (const float*)d_in[11];
    const float* Wout = (const float*)d_in[12];
    const float* bout = (const float*)d_in[13];
    const float* u      = (const float*)d_in[14];
    const float* v_bias = (const float*)d_in[15];

    float* out = (float*)d_out;
    float* out_ctx  = out;                                  // [8,1024,512]
    float* out_attn = out + (size_t)BATCH * SEQ * DMODEL;   // [8,8,1024,1024]

    static float *p_qu = nullptr, *p_qvb, *p_kh, *p_vh, *p_ph, *p_ctx, *p_pos;
    if (!p_qu) {
        cudaGetSymbolAddress((void**)&p_qu,  g_qu);
        cudaGetSymbolAddress((void**)&p_qvb, g_qvb);
        cudaGetSymbolAddress((void**)&p_kh,  g_kh);
        cudaGetSymbolAddress((void**)&p_vh,  g_vh);
        cudaGetSymbolAddress((void**)&p_ph,  g_ph);
        cudaGetSymbolAddress((void**)&p_ctx, g_ctx);
        cudaGetSymbolAddress((void**)&p_pos, g_pos);
        cudaFuncSetAttribute(k_proj4_tc,  cudaFuncAttributeMaxDynamicSharedMemorySize, P4_SMEM_BYTES);
        cudaFuncSetAttribute(k_scores_tc, cudaFuncAttributeMaxDynamicSharedMemorySize, TC_SMEM_BYTES);
        cudaFuncSetAttribute(k_av_tc,     cudaFuncAttributeMaxDynamicSharedMemorySize, AV_SMEM_BYTES);
        cudaFuncSetAttribute(k_out_tc,    cudaFuncAttributeMaxDynamicSharedMemorySize, TC_SMEM_BYTES);
    }

    // merged + pipelined tf32 projections (q dual-out, k, pos, v) in ONE launch
    dim3 gp4(DMODEL / 128, (BATCH * SEQ) / 128, 4);   // (4, 64, 4)
    k_proj4_tc<<<gp4, 256, P4_SMEM_BYTES>>>(q, k, pos_emb, v,
                                            Wq, bq, Wk, bk, Wpos, Wv, bv,
                                            u, v_bias,
                                            p_qu, p_qvb, p_kh, p_ph, p_vh);

    // tf32 tensor score GEMMs (content + pos in one launch)
    dim3 gs(SEQ / 128, SEQ / 128, 2 * BATCH * NHEAD); // (8, 8, 128)
    k_scores_tc<<<gs, 256, TC_SMEM_BYTES>>>(p_qu,  p_kh, out_attn,
                                            p_qvb, p_ph, p_pos);

    k_softmax<<<BATCH * NHEAD * SEQ, 256>>>(out_attn, p_pos, mask);

    // tf32 tensor AV
    dim3 ga(1, SEQ / 128, BATCH * NHEAD);             // (1, 8, 64)
    k_av_tc<<<ga, 256, AV_SMEM_BYTES>>>(out_attn, p_vh, p_ctx);

    // tf32 tensor output projection
    dim3 go(DMODEL / 128, (BATCH * SEQ) / 128);       // (4, 64)
    k_out_tc<<<go, 256, TC_SMEM_BYTES>>>(p_ctx, Wout, bout, out_ctx);
}

// round 8
// speedup vs baseline: 1.0887x; 1.0887x over previous
#include <cuda_runtime.h>
#include <cstdint>

#define BATCH 8
#define SEQ   1024
#define DMODEL 512
#define NHEAD 8
#define HDIM  64

// tf32 tensor-core tile config (non-pipelined kernels)
#define TCPAD 68
#define TC_SMEM_BYTES (2 * 128 * TCPAD * 4)

// pipelined AV kernel
#define AVSTR_A 36
#define AVSTR_B 68
#define AV_A_WORDS (64 * AVSTR_A)               // 2304
#define AV_B_WORDS (32 * AVSTR_B)               // 2176
#define AV_STAGE   (AV_A_WORDS + AV_B_WORDS)    // 4480 words
#define AV_SMEM_BYTES (2 * AV_STAGE * 4)        // 35840 B

static __device__ float g_qu [(size_t)BATCH*NHEAD*SEQ*HDIM];
static __device__ float g_qvb[(size_t)BATCH*NHEAD*SEQ*HDIM];
static __device__ float g_kh [(size_t)BATCH*NHEAD*SEQ*HDIM];
static __device__ float g_vh [(size_t)BATCH*NHEAD*SEQ*HDIM];
static __device__ float g_ph [(size_t)BATCH*NHEAD*SEQ*HDIM];
static __device__ float g_ctx[(size_t)BATCH*SEQ*DMODEL];
static __device__ float g_pos[(size_t)BATCH*NHEAD*SEQ*SEQ];

__device__ __forceinline__ uint32_t f2tf32(float x) {
    uint32_t t;
    asm("cvt.rna.tf32.f32 %0, %1;" : "=r"(t) : "f"(x));
    return t;
}

__device__ __forceinline__ void mma_tf32(float c[4], const uint32_t a[4], const uint32_t b[2]) {
    asm volatile(
        "mma.sync.aligned.m16n8k8.row.col.f32.tf32.tf32.f32 "
        "{%0,%1,%2,%3}, {%4,%5,%6,%7}, {%8,%9}, {%0,%1,%2,%3};"
        : "+f"(c[0]), "+f"(c[1]), "+f"(c[2]), "+f"(c[3])
        : "r"(a[0]), "r"(a[1]), "r"(a[2]), "r"(a[3]), "r"(b[0]), "r"(b[1]));
}

__device__ __forceinline__ void cp_async16(uint32_t saddr, const void* gptr) {
    asm volatile("cp.async.cg.shared.global [%0], [%1], 16;" :: "r"(saddr), "l"(gptr));
}
__device__ __forceinline__ void cp_commit() { asm volatile("cp.async.commit_group;"); }
template <int N>
__device__ __forceinline__ void cp_wait() { asm volatile("cp.async.wait_group %0;" :: "n"(N)); }

// ---------------------------------------------------------------------------
// TF32 NT projection GEMM (Round-6 proven version): Y = X W^T (+ bias)
// 128x128 block tile. Output scattered head-major, optional dual output.
// ---------------------------------------------------------------------------
__global__ __launch_bounds__(256)
void k_proj_tc(const float* __restrict__ X, const float* __restrict__ W,
               const float* __restrict__ bias,
               float* __restrict__ O1, const float* __restrict__ add1,
               float* __restrict__ O2, const float* __restrict__ add2)
{
    extern __shared__ uint32_t sm[];
    uint32_t* As = sm;                 // [128][TCPAD]
    uint32_t* Bs = sm + 128 * TCPAD;   // [128][TCPAD]

    const int tid = threadIdx.x;
    const int m0 = blockIdx.y * 128;
    const int n0 = blockIdx.x * 128;
    const int lane = tid & 31, warp = tid >> 5;
    const int wm = (warp & 1) * 64, wn = (warp >> 1) * 32;
    const int grp = lane >> 2, tig = lane & 3;

    const int lrow  = tid >> 4;        // 0..15
    const int lcol4 = (tid & 15) * 4;  // 0..60

    float acc[4][4][4] = {};

    for (int k0 = 0; k0 < DMODEL; k0 += 64) {
#pragma unroll
        for (int i = 0; i < 8; i++) {
            int r = lrow + i * 16;
            float4 a4 = *(const float4*)(X + (size_t)(m0 + r) * DMODEL + k0 + lcol4);
            float4 b4 = *(const float4*)(W + (size_t)(n0 + r) * DMODEL + k0 + lcol4);
            *(uint4*)&As[r * TCPAD + lcol4] =
                make_uint4(f2tf32(a4.x), f2tf32(a4.y), f2tf32(a4.z), f2tf32(a4.w));
            *(uint4*)&Bs[r * TCPAD + lcol4] =
                make_uint4(f2tf32(b4.x), f2tf32(b4.y), f2tf32(b4.z), f2tf32(b4.w));
        }
        __syncthreads();

#pragma unroll
        for (int ks = 0; ks < 8; ks++) {
            const int kk = ks * 8;
            uint32_t a[4][4], b[4][2];
#pragma unroll
            for (int tm = 0; tm < 4; tm++) {
                int r = wm + tm * 16 + grp;
                a[tm][0] = As[r * TCPAD + kk + tig];
                a[tm][1] = As[(r + 8) * TCPAD + kk + tig];
                a[tm][2] = As[r * TCPAD + kk + tig + 4];
                a[tm][3] = As[(r + 8) * TCPAD + kk + tig + 4];
            }
#pragma unroll
            for (int tn = 0; tn < 4; tn++) {
                int c = wn + tn * 8 + grp;
                b[tn][0] = Bs[c * TCPAD + kk + tig];
                b[tn][1] = Bs[c * TCPAD + kk + tig + 4];
            }
#pragma unroll
            for (int tm = 0; tm < 4; tm++)
#pragma unroll
                for (int tn = 0; tn < 4; tn++)
                    mma_tf32(acc[tm][tn], a[tm], b[tn]);
        }
        __syncthreads();
    }

#pragma unroll
    for (int tm = 0; tm < 4; tm++) {
#pragma unroll
        for (int tn = 0; tn < 4; tn++) {
            int j = n0 + wn + tn * 8 + tig * 2;
            int hn = j >> 6, hd = j & (HDIM - 1);
            float bj0 = bias ? bias[j] : 0.0f;
            float bj1 = bias ? bias[j + 1] : 0.0f;
#pragma unroll
            for (int half = 0; half < 2; half++) {
                int m = m0 + wm + tm * 16 + grp + half * 8;
                int bb = m >> 10, s = m & (SEQ - 1);
                float v0 = acc[tm][tn][half * 2 + 0] + bj0;
                float v1 = acc[tm][tn][half * 2 + 1] + bj1;
                size_t off = (((size_t)bb * NHEAD + hn) * SEQ + s) * HDIM + hd;
                if (add1) {
                    *(float2*)&O1[off] = make_float2(v0 + add1[j], v1 + add1[j + 1]);
                } else {
                    *(float2*)&O1[off] = make_float2(v0, v1);
                }
                if (O2) {
                    *(float2*)&O2[off] = make_float2(v0 + add2[j], v1 + add2[j + 1]);
                }
            }
        }
    }
}

// ---------------------------------------------------------------------------
// TF32 batched score GEMM (NT, K=64): C[q,k] = sum_d A[q,d]*B[k,d]
// z in [0,64): content (qu x kh) -> C0 ; z in [64,128): pos (qvb x ph) -> C1
// ---------------------------------------------------------------------------
__global__ __launch_bounds__(256)
void k_scores_tc(const float* __restrict__ A0, const float* __restrict__ B0,
                 float* __restrict__ C0,
                 const float* __restrict__ A1, const float* __restrict__ B1,
                 float* __restrict__ C1)
{
    extern __shared__ uint32_t sm[];
    uint32_t* As = sm;
    uint32_t* Bs = sm + 128 * TCPAD;

    int z = blockIdx.z;
    const float *Aall, *Ball; float* Call;
    if (z < BATCH * NHEAD) { Aall = A0; Ball = B0; Call = C0; }
    else { z -= BATCH * NHEAD; Aall = A1; Ball = B1; Call = C1; }
    const float* X = Aall + (size_t)z * SEQ * HDIM;
    const float* W = Ball + (size_t)z * SEQ * HDIM;
    float* C = Call + (size_t)z * SEQ * SEQ;

    const int tid = threadIdx.x;
    const int m0 = blockIdx.y * 128;
    const int n0 = blockIdx.x * 128;
    const int lane = tid & 31, warp = tid >> 5;
    const int wm = (warp & 1) * 64, wn = (warp >> 1) * 32;
    const int grp = lane >> 2, tig = lane & 3;

    const int lrow  = tid >> 4;
    const int lcol4 = (tid & 15) * 4;

#pragma unroll
    for (int i = 0; i < 8; i++) {
        int r = lrow + i * 16;
        float4 a4 = *(const float4*)(X + (size_t)(m0 + r) * HDIM + lcol4);
        float4 b4 = *(const float4*)(W + (size_t)(n0 + r) * HDIM + lcol4);
        *(uint4*)&As[r * TCPAD + lcol4] =
            make_uint4(f2tf32(a4.x), f2tf32(a4.y), f2tf32(a4.z), f2tf32(a4.w));
        *(uint4*)&Bs[r * TCPAD + lcol4] =
            make_uint4(f2tf32(b4.x), f2tf32(b4.y), f2tf32(b4.z), f2tf32(b4.w));
    }
    __syncthreads();

    float acc[4][4][4] = {};
#pragma unroll
    for (int ks = 0; ks < 8; ks++) {
        const int kk = ks * 8;
        uint32_t a[4][4], b[4][2];
#pragma unroll
        for (int tm = 0; tm < 4; tm++) {
            int r = wm + tm * 16 + grp;
            a[tm][0] = As[r * TCPAD + kk + tig];
            a[tm][1] = As[(r + 8) * TCPAD + kk + tig];
            a[tm][2] = As[r * TCPAD + kk + tig + 4];
            a[tm][3] = As[(r + 8) * TCPAD + kk + tig + 4];
        }
#pragma unroll
        for (int tn = 0; tn < 4; tn++) {
            int c = wn + tn * 8 + grp;
            b[tn][0] = Bs[c * TCPAD + kk + tig];
            b[tn][1] = Bs[c * TCPAD + kk + tig + 4];
        }
#pragma unroll
        for (int tm = 0; tm < 4; tm++)
#pragma unroll
            for (int tn = 0; tn < 4; tn++)
                mma_tf32(acc[tm][tn], a[tm], b[tn]);
    }

#pragma unroll
    for (int tm = 0; tm < 4; tm++) {
#pragma unroll
        for (int tn = 0; tn < 4; tn++) {
            int col = n0 + wn + tn * 8 + tig * 2;
#pragma unroll
            for (int half = 0; half < 2; half++) {
                int row = m0 + wm + tm * 16 + grp + half * 8;
                *(float2*)&C[(size_t)row * SEQ + col] =
                    make_float2(acc[tm][tn][half * 2 + 0], acc[tm][tn][half * 2 + 1]);
            }
        }
    }
}

// ---------------------------------------------------------------------------
// Pipelined TF32 batched AV GEMM (NN): Ctx[b][q][n*64+d] = sum_k attn*vh
// 64x64 block tile, K=1024 in 32-chunks, 2-stage cp.async double buffer.
// grid (1, 16, 64) = 1024 blocks. Same K order as before -> identical numerics.
// ---------------------------------------------------------------------------
__global__ __launch_bounds__(256)
void k_av_tc(const float* __restrict__ Attn, const float* __restrict__ Vall,
             float* __restrict__ Ctx)
{
    extern __shared__ float smf[];

    const int z = blockIdx.z;
    const int b = z >> 3, n = z & 7;
    const float* Ab = Attn + (size_t)z * SEQ * SEQ;
    const float* Bb = Vall + (size_t)z * SEQ * HDIM;

    const int tid = threadIdx.x;
    const int m0 = blockIdx.y * 64;
    const int lane = tid & 31, warp = tid >> 5;
    const int wm = (warp & 3) * 16, wn = (warp >> 2) * 32;  // 4x2 warps, 16x32 tiles
    const int grp = lane >> 2, tig = lane & 3;

    // loaders: A chunk 64 rows x 32 floats; B chunk 32 rows x 64 floats
    const int arow = tid >> 2, acol = (tid & 3) * 8;
    const int brow = tid >> 3, bcol = (tid & 7) * 8;

    const uint32_t s0 = (uint32_t)__cvta_generic_to_shared(smf);
    const uint32_t sA = s0 + (arow * AVSTR_A + acol) * 4;
    const uint32_t sB = s0 + (AV_A_WORDS + brow * AVSTR_B + bcol) * 4;
    const float* Agp = Ab + (size_t)(m0 + arow) * SEQ + acol;
    const float* Bgp = Bb + (size_t)brow * HDIM + bcol;

    float acc[4][4] = {};

    const int NK = SEQ / 32;  // 32 chunks

    // prologue: chunk 0 -> stage 0
    cp_async16(sA,      Agp);
    cp_async16(sA + 16, Agp + 4);
    cp_async16(sB,      Bgp);
    cp_async16(sB + 16, Bgp + 4);
    cp_commit();

    for (int t = 0; t < NK; t++) {
        const int cur = t & 1;
        if (t + 1 < NK) {
            const uint32_t off = (uint32_t)((cur ^ 1) * AV_STAGE * 4);
            const int k0 = (t + 1) * 32;
            cp_async16(sA + off,      Agp + k0);
            cp_async16(sA + off + 16, Agp + k0 + 4);
            cp_async16(sB + off,      Bgp + (size_t)k0 * HDIM);
            cp_async16(sB + off + 16, Bgp + (size_t)k0 * HDIM + 4);
            cp_commit();
            cp_wait<1>();
        } else {
            cp_wait<0>();
        }
        __syncthreads();

        const float* As = smf + cur * AV_STAGE;
        const float* Bs = As + AV_A_WORDS;

#pragma unroll
        for (int ks = 0; ks < 4; ks++) {
            const int kk = ks * 8;
            uint32_t a[4], bfr[4][2];
            {
                int r = wm + grp;
                a[0] = f2tf32(As[r * AVSTR_A + kk + tig]);
                a[1] = f2tf32(As[(r + 8) * AVSTR_A + kk + tig]);
                a[2] = f2tf32(As[r * AVSTR_A + kk + tig + 4]);
                a[3] = f2tf32(As[(r + 8) * AVSTR_A + kk + tig + 4]);
            }
#pragma unroll
            for (int tn = 0; tn < 4; tn++) {
                int c = wn + tn * 8 + grp;
                bfr[tn][0] = f2tf32(Bs[(kk + tig) * AVSTR_B + c]);
                bfr[tn][1] = f2tf32(Bs[(kk + tig + 4) * AVSTR_B + c]);
            }
#pragma unroll
            for (int tn = 0; tn < 4; tn++)
                mma_tf32(acc[tn], a, bfr[tn]);
        }
        __syncthreads();
    }

#pragma unroll
    for (int tn = 0; tn < 4; tn++) {
        int d = wn + tn * 8 + tig * 2;
#pragma unroll
        for (int half = 0; half < 2; half++) {
            int qrow = m0 + wm + grp + half * 8;
            *(float2*)&Ctx[((size_t)b * SEQ + qrow) * DMODEL + n * HDIM + d] =
                make_float2(acc[tn][half * 2 + 0], acc[tn][half * 2 + 1]);
        }
    }
}

// ---------------------------------------------------------------------------
// TF32 output NT GEMM: Out[m,j] = sum_d Ctx[m,d]*Wout[j,d] + bout[j]
// ---------------------------------------------------------------------------
__global__ __launch_bounds__(256)
void k_out_tc(const float* __restrict__ X, const float* __restrict__ W,
              const float* __restrict__ bias, float* __restrict__ Out)
{
    extern __shared__ uint32_t sm[];
    uint32_t* As = sm;
    uint32_t* Bs = sm + 128 * TCPAD;

    const int tid = threadIdx.x;
    const int m0 = blockIdx.y * 128;
    const int n0 = blockIdx.x * 128;
    const int lane = tid & 31, warp = tid >> 5;
    const int wm = (warp & 1) * 64, wn = (warp >> 1) * 32;
    const int grp = lane >> 2, tig = lane & 3;

    const int lrow  = tid >> 4;
    const int lcol4 = (tid & 15) * 4;

    float acc[4][4][4] = {};

    for (int k0 = 0; k0 < DMODEL; k0 += 64) {
#pragma unroll
        for (int i = 0; i < 8; i++) {
            int r = lrow + i * 16;
            float4 a4 = *(const float4*)(X + (size_t)(m0 + r) * DMODEL + k0 + lcol4);
            float4 b4 = *(const float4*)(W + (size_t)(n0 + r) * DMODEL + k0 + lcol4);
            *(uint4*)&As[r * TCPAD + lcol4] =
                make_uint4(f2tf32(a4.x), f2tf32(a4.y), f2tf32(a4.z), f2tf32(a4.w));
            *(uint4*)&Bs[r * TCPAD + lcol4] =
                make_uint4(f2tf32(b4.x), f2tf32(b4.y), f2tf32(b4.z), f2tf32(b4.w));
        }
        __syncthreads();

#pragma unroll
        for (int ks = 0; ks < 8; ks++) {
            const int kk = ks * 8;
            uint32_t a[4][4], b[4][2];
#pragma unroll
            for (int tm = 0; tm < 4; tm++) {
                int r = wm + tm * 16 + grp;
                a[tm][0] = As[r * TCPAD + kk + tig];
                a[tm][1] = As[(r + 8) * TCPAD + kk + tig];
                a[tm][2] = As[r * TCPAD + kk + tig + 4];
                a[tm][3] = As[(r + 8) * TCPAD + kk + tig + 4];
            }
#pragma unroll
            for (int tn = 0; tn < 4; tn++) {
                int c = wn + tn * 8 + grp;
                b[tn][0] = Bs[c * TCPAD + kk + tig];
                b[tn][1] = Bs[c * TCPAD + kk + tig + 4];
            }
#pragma unroll
            for (int tm = 0; tm < 4; tm++)
#pragma unroll
                for (int tn = 0; tn < 4; tn++)
                    mma_tf32(acc[tm][tn], a[tm], b[tn]);
        }
        __syncthreads();
    }

#pragma unroll
    for (int tm = 0; tm < 4; tm++) {
#pragma unroll
        for (int tn = 0; tn < 4; tn++) {
            int j = n0 + wn + tn * 8 + tig * 2;
            float bj0 = bias[j], bj1 = bias[j + 1];
#pragma unroll
            for (int half = 0; half < 2; half++) {
                int m = m0 + wm + tm * 16 + grp + half * 8;
                *(float2*)&Out[(size_t)m * DMODEL + j] =
                    make_float2(acc[tm][tn][half * 2 + 0] + bj0,
                                acc[tm][tn][half * 2 + 1] + bj1);
            }
        }
    }
}

// ---------------------------------------------------------------------------
// Fused relative shift + scale + mask + softmax. One block per (b,n,q) row.
// shift[q,k] = pos[q, S-1-q+k] (k<=q); 0 (k==q+1); pos[q+1, k-q-2] (k>q+1)
// ---------------------------------------------------------------------------
__global__ __launch_bounds__(256)
void k_softmax(float* __restrict__ AttnOut, const float* __restrict__ Pos,
               const int* __restrict__ Mask)
{
    const int row = blockIdx.x;
    const int q = row & (SEQ - 1);
    const int z = row >> 10;
    const int b = z >> 3;

    float* Crow = AttnOut + (size_t)row * SEQ;
    const float* P0 = Pos + ((size_t)z * SEQ + q) * SEQ;
    const float* P1 = Pos + ((size_t)z * SEQ + q + 1) * SEQ;
    const int* Mrow = Mask + ((size_t)b * SEQ + q) * SEQ;

    const float scale = 0.04419417382415922f;  // 1/sqrt(512)
    const int tid = threadIdx.x;

    float vals[4];
    float lmax = -3.0e38f;
#pragma unroll
    for (int i = 0; i < 4; i++) {
        int k = tid + i * 256;
        float c = Crow[k];
        float p;
        if (k <= q)           p = P0[SEQ - 1 - q + k];
        else if (k == q + 1)  p = 0.0f;
        else                  p = P1[k - q - 2];
        float sc = (c + p) * scale;
        if (Mrow[k] != 0) sc = -10000.0f;
        vals[i] = sc;
        lmax = fmaxf(lmax, sc);
    }

    __shared__ float red[8];
#pragma unroll
    for (int o = 16; o; o >>= 1) lmax = fmaxf(lmax, __shfl_xor_sync(0xffffffffu, lmax, o));
    if ((tid & 31) == 0) red[tid >> 5] = lmax;
    __syncthreads();
    float bmax = red[0];
#pragma unroll
    for (int w = 1; w < 8; w++) bmax = fmaxf(bmax, red[w]);

    float lsum = 0.0f;
#pragma unroll
    for (int i = 0; i < 4; i++) {
        vals[i] = __expf(vals[i] - bmax);
        lsum += vals[i];
    }
#pragma unroll
    for (int o = 16; o; o >>= 1) lsum += __shfl_xor_sync(0xffffffffu, lsum, o);
    __syncthreads();
    if ((tid & 31) == 0) red[tid >> 5] = lsum;
    __syncthreads();
    float tot = 0.0f;
#pragma unroll
    for (int w = 0; w < 8; w++) tot += red[w];
    float inv = 1.0f / tot;

#pragma unroll
    for (int i = 0; i < 4; i++) {
        int k = tid + i * 256;
        Crow[k] = vals[i] * inv;
    }
}

extern "C" void kernel_launch(void* const* d_in, const int* in_sizes, int n_in,
                              void* d_out, int out_size)
{
    const float* q       = (const float*)d_in[0];
    const float* k       = (const float*)d_in[1];
    const float* v       = (const float*)d_in[2];
    const float* pos_emb = (const float*)d_in[3];
    const int*   mask    = (const int*)d_in[4];   // bool -> int32 in harness
    const float* Wq   = (const float*)d_in[5];
    const float* bq   = (const float*)d_in[6];
    const float* Wk   = (const float*)d_in[7];
    const float* bk   = (const float*)d_in[8];
    const float* Wv   = (const float*)d_in[9];
    const float* bv   = (const float*)d_in[10];
    const float* Wpos = (const float*)d_in[11];
    const float* Wout = (const float*)d_in[12];
    const float* bout = (const float*)d_in[13];
    const float* u      = (const float*)d_in[14];
    const float* v_bias = (const float*)d_in[15];

    float* out = (float*)d_out;
    float* out_ctx  = out;                                  // [8,1024,512]
    float* out_attn = out + (size_t)BATCH * SEQ * DMODEL;   // [8,8,1024,1024]

    static float *p_qu = nullptr, *p_qvb, *p_kh, *p_vh, *p_ph, *p_ctx, *p_pos;
    if (!p_qu) {
        cudaGetSymbolAddress((void**)&p_qu,  g_qu);
        cudaGetSymbolAddress((void**)&p_qvb, g_qvb);
        cudaGetSymbolAddress((void**)&p_kh,  g_kh);
        cudaGetSymbolAddress((void**)&p_vh,  g_vh);
        cudaGetSymbolAddress((void**)&p_ph,  g_ph);
        cudaGetSymbolAddress((void**)&p_ctx, g_ctx);
        cudaGetSymbolAddress((void**)&p_pos, g_pos);
        cudaFuncSetAttribute(k_proj_tc,   cudaFuncAttributeMaxDynamicSharedMemorySize, TC_SMEM_BYTES);
        cudaFuncSetAttribute(k_scores_tc, cudaFuncAttributeMaxDynamicSharedMemorySize, TC_SMEM_BYTES);
        cudaFuncSetAttribute(k_av_tc,     cudaFuncAttributeMaxDynamicSharedMemorySize, AV_SMEM_BYTES);
        cudaFuncSetAttribute(k_out_tc,    cudaFuncAttributeMaxDynamicSharedMemorySize, TC_SMEM_BYTES);
    }

    // tf32 tensor projections (Round-6 proven path)
    dim3 gptc(DMODEL / 128, (BATCH * SEQ) / 128);   // (4, 64)
    k_proj_tc<<<gptc, 256, TC_SMEM_BYTES>>>(q,       Wq,   bq, p_qu, u, p_qvb, v_bias);
    k_proj_tc<<<gptc, 256, TC_SMEM_BYTES>>>(k,       Wk,   bk, p_kh, nullptr, nullptr, nullptr);
    k_proj_tc<<<gptc, 256, TC_SMEM_BYTES>>>(pos_emb, Wpos, nullptr, p_ph, nullptr, nullptr, nullptr);
    k_proj_tc<<<gptc, 256, TC_SMEM_BYTES>>>(v,       Wv,   bv, p_vh, nullptr, nullptr, nullptr);

    // tf32 tensor score GEMMs (content + pos in one launch)
    dim3 gs(SEQ / 128, SEQ / 128, 2 * BATCH * NHEAD); // (8, 8, 128)
    k_scores_tc<<<gs, 256, TC_SMEM_BYTES>>>(p_qu,  p_kh, out_attn,
                                            p_qvb, p_ph, p_pos);

    k_softmax<<<BATCH * NHEAD * SEQ, 256>>>(out_attn, p_pos, mask);

    // pipelined tf32 tensor AV
    dim3 ga(1, SEQ / 64, BATCH * NHEAD);              // (1, 16, 64)
    k_av_tc<<<ga, 256, AV_SMEM_BYTES>>>(out_attn, p_vh, p_ctx);

    // tf32 tensor output projection
    dim3 go(DMODEL / 128, (BATCH * SEQ) / 128);       // (4, 64)
    k_out_tc<<<go, 256, TC_SMEM_BYTES>>>(p_ctx, Wout, bout, out_ctx);
}